// round 1
// baseline (speedup 1.0000x reference)
#include <cuda_runtime.h>
#include <cuda_bf16.h>

// VisbilityMask: out[b, ch, r, c] = 1 - (normal_z(vertex r,c) >= 0)
//
// Reference reduces (scatter .set last-wins + nonneg angle weights) to the sign
// of tn_z = e0_x*e2_y - e0_y*e2_x of ONE face per vertex:
//   r>=1,c>=1 : f2 of cell (r-1,c-1): v0=(r-1,c) v1=(r,c-1) v2=(r,c)
//   r==0,c>=1 : f1 of cell (0,c-1):  v0=(0,c-1) v1=(1,c-1) v2=(0,c)
//   r>=1,c==0 : f2 of cell (r-1,0):  v0=(r-1,1) v1=(r,0)   v2=(r,1)
//   (0,0)     : f1 of cell (0,0):    v0=(0,0)   v1=(1,0)   v2=(0,1)
// e0 = P(v1)-P(v0), e2 = P(v1)-P(v2); only x,y planes of X are needed.

#define G     512
#define NV    (G * G)          // 262144 vertices
#define BATCH 4

__global__ __launch_bounds__(256, 8)
void visibility_mask_kernel(const float* __restrict__ X, float* __restrict__ out)
{
    const int tid = blockIdx.x * blockDim.x + threadIdx.x;  // 0 .. BATCH*NV-1
    const int b = tid >> 18;          // NV = 2^18
    const int n = tid & (NV - 1);
    const int r = n >> 9;             // G = 2^9
    const int c = n & (G - 1);

    const float* xs = X + (size_t)b * 3 * NV;        // x-plane
    const float* ys = xs + NV;                        // y-plane

    // i1 = shared vertex v1, edges e0 = P(i1)-P(i0), e2 = P(i1)-P(i2)
    int i0, i1, i2;
    if (r > 0) {
        if (c > 0) { i1 = n - 1;     i0 = n - G;     i2 = n;     }
        else       { i1 = n;         i0 = n - G + 1; i2 = n + 1; }
    } else {
        if (c > 0) { i1 = n + G - 1; i0 = n - 1;     i2 = n;     }
        else       { i1 = G;         i0 = 0;         i2 = 1;     }
    }

    const float p1x = __ldg(xs + i1), p1y = __ldg(ys + i1);
    const float e0x = p1x - __ldg(xs + i0);
    const float e0y = p1y - __ldg(ys + i0);
    const float e2x = p1x - __ldg(xs + i2);
    const float e2y = p1y - __ldg(ys + i2);

    // tn_z with explicit round-to-nearest mul/sub: no FMA contraction, so the
    // sign matches XLA's mul,mul,sub sequence bit-for-bit.
    const float tnz = __fsub_rn(__fmul_rn(e0x, e2y), __fmul_rn(e0y, e2x));
    const float o = (tnz >= 0.0f) ? 0.0f : 1.0f;

    float* ob = out + (size_t)b * 3 * NV + n;
    ob[0]      = o;
    ob[NV]     = o;
    ob[2 * NV] = o;
}

extern "C" void kernel_launch(void* const* d_in, const int* in_sizes, int n_in,
                              void* d_out, int out_size)
{
    const float* X = (const float*)d_in[0];   // [BATCH, 3, NV] float32
    // d_in[1] (faces) is provably unused by the reduced computation.
    float* out = (float*)d_out;               // [BATCH, 3, G, G] float32

    const int total = BATCH * NV;             // 1,048,576
    visibility_mask_kernel<<<total / 256, 256>>>(X, out);
}

// round 3
// speedup vs baseline: 1.0252x; 1.0252x over previous
#include <cuda_runtime.h>
#include <cuda_bf16.h>

// VisbilityMask: out[b, ch, r, c] = 1 - (tn_z(vertex r,c) >= 0)
//
// Reduction of the reference (scatter .set last-wins + nonnegative angle
// weights => only the SIGN of one face normal's z matters per vertex):
//   r>=1, c>=1 : face f2 of cell (r-1,c-1): p1=(r,c-1) p0=(r-1,c) p2=(r,c)
//   r==0, c>=1 : face f1 of cell (0,c-1):   p1=(1,c-1) p0=(0,c-1) p2=(0,c)
//   c==0       : same face as c==1  =>  mask[r][0] == mask[r][1]
// e0 = P(p1)-P(p0), e2 = P(p1)-P(p2), tn_z = e0x*e2y - e0y*e2x (x,y only).
//
// 1 thread = 4 consecutive c. Exactly 4x LDG.128 per thread (front-batched);
// c-1 neighbors come from __shfl_up within the warp (lane0 does 2-4 LDG.32).

#define G     512
#define NV    (G * G)          // 262144
#define BATCH 4
#define FULL  0xFFFFFFFFu

__global__ __launch_bounds__(256, 8)
void visibility_mask_v4(const float* __restrict__ X, float* __restrict__ out)
{
    const int tid = blockIdx.x * blockDim.x + threadIdx.x;  // 0 .. BATCH*NV/4-1
    const int b  = tid >> 16;            // 65536 quads per batch
    const int q  = tid & 65535;
    const int r  = q >> 7;               // 128 quads per row (4 warps per row)
    const int cq = q & 127;              // quad index; c0 = 4*cq
    const int lane = threadIdx.x & 31;

    const float* xs = X + (size_t)b * 3 * NV;   // x-plane
    const float* ys = xs + NV;                   // y-plane

    const int ro = (r > 0) ? (r - 1) : 1;        // "other" row

    // Front-batched vector loads: own row (A) and other row (B), x and y.
    const float4 ax = ((const float4*)(xs + (size_t)r  * G))[cq];
    const float4 ay = ((const float4*)(ys + (size_t)r  * G))[cq];
    const float4 bx = ((const float4*)(xs + (size_t)ro * G))[cq];
    const float4 by = ((const float4*)(ys + (size_t)ro * G))[cq];

    // c0-1 neighbor values via warp shuffle of the previous lane's .w elements.
    float axm1 = __shfl_up_sync(FULL, ax.w, 1);
    float aym1 = __shfl_up_sync(FULL, ay.w, 1);
    float bxm1 = __shfl_up_sync(FULL, bx.w, 1);
    float bym1 = __shfl_up_sync(FULL, by.w, 1);

    if (lane == 0 && cq > 0) {           // warp boundary inside a row: real loads
        const int cm1 = 4 * cq - 1;
        axm1 = __ldg(xs + (size_t)r * G + cm1);
        aym1 = __ldg(ys + (size_t)r * G + cm1);
        if (r == 0) {
            bxm1 = __ldg(xs + (size_t)G + cm1);
            bym1 = __ldg(ys + (size_t)G + cm1);
        }
    }
    // (cq==0: *m1 values are garbage but o[0] is overwritten by o[1] below.)

    float p1x[4], p1y[4], p0x[4], p0y[4], p2x[4], p2y[4];
    if (r > 0) {   // warp-uniform branch
        // p1 = A[c-1], p0 = B[c], p2 = A[c]
        p1x[0]=axm1;  p1y[0]=aym1;  p0x[0]=bx.x; p0y[0]=by.x; p2x[0]=ax.x; p2y[0]=ay.x;
        p1x[1]=ax.x;  p1y[1]=ay.x;  p0x[1]=bx.y; p0y[1]=by.y; p2x[1]=ax.y; p2y[1]=ay.y;
        p1x[2]=ax.y;  p1y[2]=ay.y;  p0x[2]=bx.z; p0y[2]=by.z; p2x[2]=ax.z; p2y[2]=ay.z;
        p1x[3]=ax.z;  p1y[3]=ay.z;  p0x[3]=bx.w; p0y[3]=by.w; p2x[3]=ax.w; p2y[3]=ay.w;
    } else {
        // p1 = B[c-1], p0 = A[c-1], p2 = A[c]   (B = row 1, A = row 0)
        p1x[0]=bxm1;  p1y[0]=bym1;  p0x[0]=axm1; p0y[0]=aym1; p2x[0]=ax.x; p2y[0]=ay.x;
        p1x[1]=bx.x;  p1y[1]=by.x;  p0x[1]=ax.x; p0y[1]=ay.x; p2x[1]=ax.y; p2y[1]=ay.y;
        p1x[2]=bx.y;  p1y[2]=by.y;  p0x[2]=ax.y; p0y[2]=ay.y; p2x[2]=ax.z; p2y[2]=ay.z;
        p1x[3]=bx.z;  p1y[3]=by.z;  p0x[3]=ax.z; p0y[3]=ay.z; p2x[3]=ax.w; p2y[3]=ay.w;
    }

    float o[4];
    #pragma unroll
    for (int j = 0; j < 4; j++) {
        const float e0x = p1x[j] - p0x[j];
        const float e0y = p1y[j] - p0y[j];
        const float e2x = p1x[j] - p2x[j];
        const float e2y = p1y[j] - p2y[j];
        // explicit rn mul/sub: forbid FMA contraction so the sign matches XLA
        const float tnz = __fsub_rn(__fmul_rn(e0x, e2y), __fmul_rn(e0y, e2x));
        o[j] = (tnz >= 0.0f) ? 0.0f : 1.0f;
    }
    if (cq == 0) o[0] = o[1];   // mask[r][0] == mask[r][1] (same face)

    const float4 o4 = make_float4(o[0], o[1], o[2], o[3]);
    float* ob = out + (size_t)b * 3 * NV + (size_t)r * G;
    ((float4*)(ob))[cq]          = o4;
    ((float4*)(ob + NV))[cq]     = o4;
    ((float4*)(ob + 2 * NV))[cq] = o4;
}

extern "C" void kernel_launch(void* const* d_in, const int* in_sizes, int n_in,
                              void* d_out, int out_size)
{
    const float* X = (const float*)d_in[0];   // [BATCH, 3, NV] float32
    float* out = (float*)d_out;               // [BATCH, 3, G, G] float32

    const int total = BATCH * NV / 4;         // 262144 threads
    visibility_mask_v4<<<total / 256, 256>>>(X, out);
}